// round 7
// baseline (speedup 1.0000x reference)
#include <cuda_runtime.h>
#include <cuda_fp16.h>
#include <cstdint>

// ============================================================================
// out[m,b,o] = relu( sum_i inp[m,b,i] * w[m,i,o] + bias[m,o] )
// M=8, B=4096, D_IN=512, D_OUT=512, fp32.
//
// R7: A consumed as fp32 directly (no convert_a kernel): cp.async fp32 A tile,
//     fragments built via ld.shared.v2.f32 + cvt.rn.f16x2.f32.
//     B from 4MB fp16 transposed weights (convert_w) via ldmatrix.
//     4 warps/CTA (2x2 of 64x64), KC=64, NSTAGE=2 (104KB smem, 2 CTAs/SM),
//     fragment double-buffering, fused bias+relu epilogue.
// ============================================================================

static constexpr int MDIM = 8;
static constexpr int BDIM = 4096;
static constexpr int DIN  = 512;
static constexpr int DOUT = 512;

static constexpr int BM = 128;
static constexpr int BN = 128;
static constexpr int KC = 64;              // K per pipeline chunk
static constexpr int NCHUNK = DIN / KC;    // 8
static constexpr int NSTAGE = 2;
static constexpr int THREADS = 128;        // 4 warps, 2x2 grid of 64x64 tiles

// A rows: 64 fp32 = 256B data, padded to 272B (<=2-way LDS.64 conflicts).
// B rows: 64 fp16 = 128B data, padded to 144B (ldmatrix conflict-free).
static constexpr int AROWB = 272;
static constexpr int BROWB = 144;
static constexpr int A_REGION = BM * AROWB;            // 34816
static constexpr int B_REGION = BN * BROWB;            // 18432
static constexpr int STAGE_BYTES = A_REGION + B_REGION;    // 53248
static constexpr int SMEM_TOTAL  = NSTAGE * STAGE_BYTES;   // 106496

// fp16 transposed weights scratch (4 MB; static device global)
__device__ __align__(16) __half g_Bh[(size_t)MDIM * DOUT * DIN];

// ---------------- helpers ----------------

__device__ __forceinline__ uint32_t smem_u32(const void* p) {
    uint32_t a;
    asm("{ .reg .u64 t; cvta.to.shared.u64 t, %1; cvt.u32.u64 %0, t; }"
        : "=r"(a) : "l"(p));
    return a;
}

__device__ __forceinline__ void cp16(uint32_t dst, const void* src) {
    asm volatile("cp.async.cg.shared.global [%0], [%1], 16;"
                 :: "r"(dst), "l"(src) : "memory");
}

__device__ __forceinline__ void ldmx4(uint32_t* r, uint32_t addr) {
    asm volatile("ldmatrix.sync.aligned.m8n8.x4.shared.b16 {%0,%1,%2,%3}, [%4];"
                 : "=r"(r[0]), "=r"(r[1]), "=r"(r[2]), "=r"(r[3]) : "r"(addr));
}

// load float2 from smem, convert to packed half2 (lo = lower address/column)
__device__ __forceinline__ uint32_t lds_cvt_h2(uint32_t addr) {
    float f0, f1;
    asm volatile("ld.shared.v2.f32 {%0,%1}, [%2];"
                 : "=f"(f0), "=f"(f1) : "r"(addr));
    uint32_t d;
    asm("cvt.rn.f16x2.f32 %0, %2, %1;" : "=r"(d) : "f"(f0), "f"(f1));
    return d;
}

__device__ __forceinline__ void mma_f16(float* c, const uint32_t* a,
                                        const uint32_t* b) {
    asm volatile(
        "mma.sync.aligned.m16n8k16.row.col.f32.f16.f16.f32 "
        "{%0,%1,%2,%3}, {%4,%5,%6,%7}, {%8,%9}, {%0,%1,%2,%3};"
        : "+f"(c[0]), "+f"(c[1]), "+f"(c[2]), "+f"(c[3])
        : "r"(a[0]), "r"(a[1]), "r"(a[2]), "r"(a[3]),
          "r"(b[0]), "r"(b[1]));
}

// ---------------- preprocessing: w[m][i][o] fp32 -> g_Bh[m][o][i] fp16 -------

__global__ void __launch_bounds__(256) convert_w_kernel(const float* __restrict__ w) {
    __shared__ float tile[32][33];
    const int m  = blockIdx.z;
    const int o0 = blockIdx.x * 32;
    const int i0 = blockIdx.y * 32;
    const int tx = threadIdx.x;
    const int ty = threadIdx.y;
    const float* wm = w + (size_t)m * DIN * DOUT;
    __half* bm = g_Bh + (size_t)m * DOUT * DIN;
#pragma unroll
    for (int j = 0; j < 32; j += 8)
        tile[ty + j][tx] = wm[(size_t)(i0 + ty + j) * DOUT + o0 + tx];
    __syncthreads();
#pragma unroll
    for (int j = 0; j < 32; j += 8)
        bm[(size_t)(o0 + ty + j) * DIN + i0 + tx] = __float2half_rn(tile[tx][ty + j]);
}

// ---------------- main GEMM kernel ----------------

__global__ void __launch_bounds__(THREADS, 2)
fused_gemm_f16_kernel(const float* __restrict__ inp,
                      const float* __restrict__ bias,
                      float* __restrict__ out) {
    extern __shared__ char smem[];
    const uint32_t sbase = smem_u32(smem);

    const int tid  = threadIdx.x;
    const int warp = tid >> 5;
    const int lane = tid & 31;
    const int gid  = lane >> 2;
    const int tig  = lane & 3;
    const int wr   = warp >> 1;      // warp row (0..1) -> 64 rows
    const int wc   = warp & 1;       // warp col (0..1) -> 64 cols

    const int tn = blockIdx.x;       // D_OUT tile (0..3) — fastest: A reuse in L2
    const int tm = blockIdx.y;       // B-dim tile (0..31)
    const int mm = blockIdx.z;       // matrix (0..7)

    const float*  __restrict__ Ag = inp  + ((size_t)mm * BDIM + (size_t)tm * BM) * DIN;
    const __half* __restrict__ Bg = g_Bh + ((size_t)mm * DOUT + (size_t)tn * BN) * DIN;

    float acc[4][8][4];
#pragma unroll
    for (int mt = 0; mt < 4; ++mt)
#pragma unroll
        for (int nt = 0; nt < 8; ++nt)
#pragma unroll
            for (int i = 0; i < 4; ++i) acc[mt][nt][i] = 0.0f;

    // ---- async loader for chunk c into stage s: A fp32 128x64, B fp16 128x64
    auto issue_chunk = [&](int c, int s) {
        const uint32_t sA = sbase + s * STAGE_BYTES;
        const uint32_t sB = sA + A_REGION;
#pragma unroll
        for (int it = 0; it < 16; ++it) {
            int idx = tid + it * THREADS;        // 0..2047
            int row = idx >> 4;                  // 0..127
            int q   = idx & 15;                  // 16B sixteenth of 256B row
            cp16(sA + row * AROWB + q * 16, Ag + (size_t)row * DIN + c * KC + q * 4);
        }
#pragma unroll
        for (int it = 0; it < 8; ++it) {
            int idx = tid + it * THREADS;        // 0..1023
            int n = idx >> 3;
            int q = idx & 7;
            cp16(sB + n * BROWB + q * 16, Bg + (size_t)n * DIN + c * KC + q * 8);
        }
        asm volatile("cp.async.commit_group;" ::: "memory");
    };

    // ---- per-lane offsets
    // A (fp32 smem): thread reads float2 at (row, col): base row wr*64+gid, col 2*tig
    const uint32_t a_lane_base =
        (uint32_t)((wr * 64 + gid) * AROWB + tig * 8);
    // B x4 ldmatrix pair p: rows wc*64 + p*16 + (l&7) + ((l>>4)<<3), colByte ((l>>3)&1)*16
    const uint32_t b_lane_off =
        (uint32_t)((wc * 64 + (lane & 7) + ((lane >> 4) << 3)) * BROWB +
                   ((lane >> 3) & 1) * 16);

    // A fragment loader: tile mt, k-step ks (k0 = ks*16) from stage base sA
    auto lda_tile = [&](uint32_t* f, uint32_t sA, int mt, int ks) {
        const uint32_t a = sA + a_lane_base + (uint32_t)(mt * 16 * AROWB + ks * 64);
        f[0] = lds_cvt_h2(a);
        f[1] = lds_cvt_h2(a + 8 * AROWB);
        f[2] = lds_cvt_h2(a + 32);
        f[3] = lds_cvt_h2(a + 8 * AROWB + 32);
    };

    // ---- prologue
    issue_chunk(0, 0);

    // ---- main loop: one barrier per chunk, frag double-buffer inside
#pragma unroll 1
    for (int c = 0; c < NCHUNK; ++c) {
        asm volatile("cp.async.wait_group 0;" ::: "memory");
        __syncthreads();   // chunk c visible; all warps done reading stage c-1

        const uint32_t sA = sbase + (c & 1) * STAGE_BYTES;
        const uint32_t sB = sA + A_REGION;

        // loads for chunk c+1 overlap this whole chunk's compute
        if (c + 1 < NCHUNK)
            issue_chunk(c + 1, (c + 1) & 1);

        uint32_t af[2][4][4], bf[2][4][4];

        // preload kstep 0
#pragma unroll
        for (int mt = 0; mt < 4; ++mt)
            lda_tile(af[0][mt], sA, mt, 0);
#pragma unroll
        for (int p = 0; p < 4; ++p)
            ldmx4(bf[0][p], sB + b_lane_off + p * (16 * BROWB));

#pragma unroll
        for (int ks = 0; ks < 4; ++ks) {
            const int cur = ks & 1, nxt = cur ^ 1;
            if (ks < 3) {
#pragma unroll
                for (int mt = 0; mt < 4; ++mt)
                    lda_tile(af[nxt][mt], sA, mt, ks + 1);
#pragma unroll
                for (int p = 0; p < 4; ++p)
                    ldmx4(bf[nxt][p], sB + b_lane_off + p * (16 * BROWB) +
                                      (uint32_t)(ks + 1) * 32);
            }
#pragma unroll
            for (int mt = 0; mt < 4; ++mt)
#pragma unroll
                for (int nt = 0; nt < 8; ++nt)
                    mma_f16(acc[mt][nt], af[cur][mt], &bf[cur][nt >> 1][(nt & 1) * 2]);
        }
    }

    // ---- epilogue: bias + relu, float2 stores
    const float* brow = bias + (size_t)mm * DOUT + tn * BN + wc * 64;
    float2 bv[8];
#pragma unroll
    for (int nt = 0; nt < 8; ++nt)
        bv[nt] = *reinterpret_cast<const float2*>(brow + nt * 8 + tig * 2);

#pragma unroll
    for (int mt = 0; mt < 4; ++mt) {
        const int r0 = tm * BM + wr * 64 + mt * 16 + gid;
        float* o0 = out + ((size_t)mm * BDIM + r0) * DOUT + tn * BN + wc * 64;
        float* o1 = o0 + 8 * DOUT;
#pragma unroll
        for (int nt = 0; nt < 8; ++nt) {
            float2 v0, v1;
            v0.x = fmaxf(acc[mt][nt][0] + bv[nt].x, 0.0f);
            v0.y = fmaxf(acc[mt][nt][1] + bv[nt].y, 0.0f);
            v1.x = fmaxf(acc[mt][nt][2] + bv[nt].x, 0.0f);
            v1.y = fmaxf(acc[mt][nt][3] + bv[nt].y, 0.0f);
            *reinterpret_cast<float2*>(o0 + nt * 8 + tig * 2) = v0;
            *reinterpret_cast<float2*>(o1 + nt * 8 + tig * 2) = v1;
        }
    }
}

// ---------------------------------------------------------------------------

extern "C" void kernel_launch(void* const* d_in, const int* in_sizes, int n_in,
                              void* d_out, int out_size) {
    const float* inp  = (const float*)d_in[0];   // [8, 4096, 512]
    const float* w    = (const float*)d_in[1];   // [8, 512, 512]
    const float* bias = (const float*)d_in[2];   // [8, 512]
    float* out = (float*)d_out;                  // [8, 4096, 512]
    (void)in_sizes; (void)n_in; (void)out_size;

    // 1) weights fp32 -> fp16 transposed [m][o][i] (4 MB)
    convert_w_kernel<<<dim3(DOUT / 32, DIN / 32, MDIM), dim3(32, 8)>>>(w);

    // 2) fused fp16 tensor-core GEMM (A consumed as fp32) + bias + relu
    cudaFuncSetAttribute(fused_gemm_f16_kernel,
                         cudaFuncAttributeMaxDynamicSharedMemorySize, SMEM_TOTAL);
    dim3 grid(DOUT / BN, BDIM / BM, MDIM);   // (4, 32, 8) = 1024 CTAs
    fused_gemm_f16_kernel<<<grid, THREADS, SMEM_TOTAL>>>(inp, bias, out);
}